// round 4
// baseline (speedup 1.0000x reference)
#include <cuda_runtime.h>

#define Hh 512
#define Ww 512
#define Bb 8
#define HW (Hh*Ww)

#define TH 16
#define TW 64
#define CHUNK 4
#define Y1H (TH+2)   // 18
#define Y1W 66       // real cols needed
#define Y1WP 68      // padded stride (mult of 4 -> 16B aligned rows)
#define XH  (TH+4)   // 20
#define XW  72       // padded halo row
#define WP  20       // padded stride for 18 conv2 output channels

__global__ __launch_bounds__(256, 2)
void fused_deform_kernel(const float* __restrict__ x,
                         const float* __restrict__ w1, const float* __restrict__ b1,
                         const float* __restrict__ w2, const float* __restrict__ b2,
                         const float* __restrict__ wd, const float* __restrict__ bd,
                         float* __restrict__ out)
{
    __shared__ __align__(16) float sx[3][XH][XW];          // 17.3 KB
    __shared__ __align__(16) float sy1[CHUNK][Y1H][Y1WP];  // 19.6 KB
    __shared__ __align__(16) float sw2[CHUNK * 9 * WP];    //  2.9 KB
    __shared__ __align__(16) float sw1[64 * 27];           //  6.9 KB
    __shared__ __align__(16) float4 sw1t[27];              // chunk weights [tap][4cl]
    __shared__ float sb1[64];
    __shared__ float swd[81];
    __shared__ float sbd[3];

    const int tid = threadIdx.x;
    const int b   = blockIdx.z;
    const int y0  = blockIdx.y * TH;
    const int x0  = blockIdx.x * TW;

    // ---- stage constants ----
    for (int i = tid; i < 64 * 27; i += 256) sw1[i] = __ldg(&w1[i]);
    if (tid < 64) sb1[tid] = __ldg(&b1[tid]);
    if (tid < 81) swd[tid] = __ldg(&wd[tid]);
    if (tid < 3)  sbd[tid] = __ldg(&bd[tid]);

    // ---- stage x halo (rows y0-2..y0+17, cols x0-2..x0+65, zero padded) ----
    for (int i = tid; i < 3 * XH * XW; i += 256) {
        int c  = i / (XH * XW);
        int rr = (i / XW) % XH;
        int cc = i % XW;
        int gy = y0 - 2 + rr;
        int gx = x0 - 2 + cc;
        float v = 0.f;
        if (gy >= 0 && gy < Hh && gx >= 0 && gx < Ww)
            v = __ldg(&x[(size_t)(b * 3 + c) * HW + gy * Ww + gx]);
        sx[c][rr][cc] = v;
    }

    // ---- per-thread offset accumulators: 4 px x 18 channels ----
    float acc[18][4];
#pragma unroll
    for (int co = 0; co < 18; co++) {
        float bv = __ldg(&b2[co]);
        acc[co][0] = bv; acc[co][1] = bv; acc[co][2] = bv; acc[co][3] = bv;
    }

    const int r     = tid >> 4;        // 0..15 : tile row
    const int cbase = (tid & 15) * 4;  // 0..60 : tile col group

    for (int ch0 = 0; ch0 < 64; ch0 += CHUNK) {
        __syncthreads();  // previous chunk's sy1/sw2/sw1t fully consumed

        // stage transposed conv2 weight chunk: [cl][tap][co]
        for (int i = tid; i < 18 * CHUNK * 9; i += 256) {
            int co = i / (CHUNK * 9);
            int rr = i % (CHUNK * 9);        // cl*9 + tap
            sw2[rr * WP + co] = __ldg(&w2[co * 576 + ch0 * 9 + rr]);
        }
        // stage transposed conv1 chunk weights: sw1t[tap] = {cl0,cl1,cl2,cl3}
        if (tid < 108) {
            int t  = tid >> 2;
            int cl = tid & 3;
            ((float*)sw1t)[t * 4 + cl] = sw1[(ch0 + cl) * 27 + t];
        }
        __syncthreads();

        // conv1 (+ReLU, image-masked): one task = 4 channels x 4 px.
        // Input channels processed outermost -> only v[3][6] (18 regs) live.
        for (int task = tid; task < Y1H * 17; task += 256) {
            int row = task / 17;
            int c0  = (task % 17) * 4;

            float a[4][4];
#pragma unroll
            for (int cl = 0; cl < 4; cl++) {
                float bv = sb1[ch0 + cl];
                a[cl][0] = bv; a[cl][1] = bv; a[cl][2] = bv; a[cl][3] = bv;
            }

#pragma unroll
            for (int c = 0; c < 3; c++) {
                float v[3][6];
#pragma unroll
                for (int dy = 0; dy < 3; dy++) {
                    float4 p4 = *(const float4*)&sx[c][row + dy][c0];
                    float2 p2 = *(const float2*)&sx[c][row + dy][c0 + 4];
                    v[dy][0] = p4.x; v[dy][1] = p4.y;
                    v[dy][2] = p4.z; v[dy][3] = p4.w;
                    v[dy][4] = p2.x; v[dy][5] = p2.y;
                }
#pragma unroll
                for (int t9 = 0; t9 < 9; t9++) {
                    const int dy = t9 / 3, dx = t9 % 3;
                    float4 w4 = sw1t[c * 9 + t9];
#pragma unroll
                    for (int j = 0; j < 4; j++) {
                        float vv = v[dy][dx + j];
                        a[0][j] = fmaf(vv, w4.x, a[0][j]);
                        a[1][j] = fmaf(vv, w4.y, a[1][j]);
                        a[2][j] = fmaf(vv, w4.z, a[2][j]);
                        a[3][j] = fmaf(vv, w4.w, a[3][j]);
                    }
                }
            }

            int gyy = y0 - 1 + row;
            bool okY = (gyy >= 0) && (gyy < Hh);
            bool okJ[4];
#pragma unroll
            for (int j = 0; j < 4; j++) {
                int col = c0 + j;
                int gx  = x0 - 1 + col;
                okJ[j] = okY && (col < Y1W) && (gx >= 0) && (gx < Ww);
            }
#pragma unroll
            for (int cl = 0; cl < 4; cl++) {
                float4 rv;
                rv.x = okJ[0] ? fmaxf(a[cl][0], 0.f) : 0.f;
                rv.y = okJ[1] ? fmaxf(a[cl][1], 0.f) : 0.f;
                rv.z = okJ[2] ? fmaxf(a[cl][2], 0.f) : 0.f;
                rv.w = okJ[3] ? fmaxf(a[cl][3], 0.f) : 0.f;
                *(float4*)&sy1[cl][row][c0] = rv;
            }
        }
        __syncthreads();

        // conv2 accumulate: 4 cin x 9 taps x 18 co x 4 px
#pragma unroll 1
        for (int cl = 0; cl < CHUNK; cl++) {
            float n[3][6];
#pragma unroll
            for (int r2 = 0; r2 < 3; r2++) {
                float4 p4 = *(const float4*)&sy1[cl][r + r2][cbase];
                float2 p2 = *(const float2*)&sy1[cl][r + r2][cbase + 4];
                n[r2][0] = p4.x; n[r2][1] = p4.y; n[r2][2] = p4.z;
                n[r2][3] = p4.w; n[r2][4] = p2.x; n[r2][5] = p2.y;
            }
#pragma unroll
            for (int t = 0; t < 9; t++) {
                const int ky = t / 3, kx = t % 3;
                const float* wp = &sw2[(cl * 9 + t) * WP];
                float w[18];
#pragma unroll
                for (int q = 0; q < 4; q++) {
                    float4 w4 = *(const float4*)(wp + 4 * q);
                    w[4*q] = w4.x; w[4*q+1] = w4.y; w[4*q+2] = w4.z; w[4*q+3] = w4.w;
                }
                float2 w2v = *(const float2*)(wp + 16);
                w[16] = w2v.x; w[17] = w2v.y;
#pragma unroll
                for (int co = 0; co < 18; co++) {
                    acc[co][0] = fmaf(n[ky][kx + 0], w[co], acc[co][0]);
                    acc[co][1] = fmaf(n[ky][kx + 1], w[co], acc[co][1]);
                    acc[co][2] = fmaf(n[ky][kx + 2], w[co], acc[co][2]);
                    acc[co][3] = fmaf(n[ky][kx + 3], w[co], acc[co][3]);
                }
            }
        }
    }

    // ---- deformable conv epilogue: offsets live in acc ----
    const int gy = y0 + r;
    const float* xb = x + (size_t)(b * 3) * HW;
    float o[3][4];
#pragma unroll
    for (int j = 0; j < 4; j++) {
        int gx = x0 + cbase + j;
        float a0 = sbd[0], a1 = sbd[1], a2 = sbd[2];
#pragma unroll
        for (int k = 0; k < 9; k++) {
            float dy = acc[2 * k][j];
            float dx = acc[2 * k + 1][j];
            float ys = (float)(gy + k / 3 - 1) + dy;
            float xs = (float)(gx + k % 3 - 1) + dx;
            float yf = floorf(ys), xf = floorf(xs);
            int iy0 = (int)yf, ix0 = (int)xf;
            float fy = ys - yf, fx = xs - xf;
            float s0 = 0.f, s1 = 0.f, s2 = 0.f;
#pragma unroll
            for (int cy = 0; cy < 2; cy++)
#pragma unroll
                for (int cx = 0; cx < 2; cx++) {
                    int iy = iy0 + cy, ix = ix0 + cx;
                    float wgt = (cy ? fy : 1.f - fy) * (cx ? fx : 1.f - fx);
                    bool ok = (iy >= 0) && (iy < Hh) && (ix >= 0) && (ix < Ww);
                    wgt = ok ? wgt : 0.f;
                    int idx = min(max(iy, 0), Hh - 1) * Ww + min(max(ix, 0), Ww - 1);
                    s0 = fmaf(wgt, __ldg(xb + idx), s0);
                    s1 = fmaf(wgt, __ldg(xb + HW + idx), s1);
                    s2 = fmaf(wgt, __ldg(xb + 2 * HW + idx), s2);
                }
            a0 = fmaf(s0, swd[ 0 + k], fmaf(s1, swd[ 9 + k], fmaf(s2, swd[18 + k], a0)));
            a1 = fmaf(s0, swd[27 + k], fmaf(s1, swd[36 + k], fmaf(s2, swd[45 + k], a1)));
            a2 = fmaf(s0, swd[54 + k], fmaf(s1, swd[63 + k], fmaf(s2, swd[72 + k], a2)));
        }
        o[0][j] = a0; o[1][j] = a1; o[2][j] = a2;
    }
#pragma unroll
    for (int c = 0; c < 3; c++) {
        float4 v;
        v.x = o[c][0]; v.y = o[c][1]; v.z = o[c][2]; v.w = o[c][3];
        *(float4*)&out[(size_t)(b * 3 + c) * HW + (size_t)gy * Ww + x0 + cbase] = v;
    }
}

extern "C" void kernel_launch(void* const* d_in, const int* in_sizes, int n_in,
                              void* d_out, int out_size)
{
    const float* x  = (const float*)d_in[0];
    const float* w1 = (const float*)d_in[1];
    const float* b1 = (const float*)d_in[2];
    const float* w2 = (const float*)d_in[3];
    const float* b2 = (const float*)d_in[4];
    const float* wd = (const float*)d_in[5];
    const float* bd = (const float*)d_in[6];
    float* out = (float*)d_out;

    dim3 grid(Ww / TW, Hh / TH, Bb);   // 8 x 32 x 8 = 2048 blocks
    fused_deform_kernel<<<grid, 256>>>(x, w1, b1, w2, b2, wd, bd, out);
}

// round 5
// speedup vs baseline: 1.6021x; 1.6021x over previous
#include <cuda_runtime.h>

#define Hh 512
#define Ww 512
#define Bb 8
#define HW (Hh*Ww)

#define TH 16
#define TW 64
#define NT 512
#define CHUNK 4
#define Y1H (TH+2)   // 18
#define Y1W 66       // real cols needed
#define Y1WP 68      // padded stride (16B-aligned rows)
#define XH  (TH+4)   // 20
#define XW  72       // padded halo row
#define WP  20       // padded stride for 18 conv2 output channels

__global__ __launch_bounds__(NT, 1)
void fused_deform_kernel(const float* __restrict__ x,
                         const float* __restrict__ w1, const float* __restrict__ b1,
                         const float* __restrict__ w2, const float* __restrict__ b2,
                         const float* __restrict__ wd, const float* __restrict__ bd,
                         float* __restrict__ out)
{
    __shared__ __align__(16) float sx[3][XH][XW];          // 17.3 KB
    __shared__ __align__(16) float sy1[CHUNK][Y1H][Y1WP];  // 19.6 KB
    __shared__ __align__(16) float sw2[CHUNK * 9 * WP];    //  2.9 KB
    __shared__ __align__(16) float sw1[64 * 27];           //  6.9 KB
    __shared__ __align__(16) float4 sw1t[27];              // chunk weights [tap][4cl]
    __shared__ float sb1[64];
    __shared__ float swd[81];
    __shared__ float sbd[3];

    const int tid = threadIdx.x;
    const int b   = blockIdx.z;
    const int y0  = blockIdx.y * TH;
    const int x0  = blockIdx.x * TW;

    // ---- stage constants ----
    for (int i = tid; i < 64 * 27; i += NT) sw1[i] = __ldg(&w1[i]);
    if (tid < 64) sb1[tid] = __ldg(&b1[tid]);
    if (tid < 81) swd[tid] = __ldg(&wd[tid]);
    if (tid < 3)  sbd[tid] = __ldg(&bd[tid]);

    // ---- stage x halo (rows y0-2..y0+17, cols x0-2..x0+65, zero padded) ----
    for (int i = tid; i < 3 * XH * XW; i += NT) {
        int c  = i / (XH * XW);
        int rr = (i / XW) % XH;
        int cc = i % XW;
        int gy = y0 - 2 + rr;
        int gx = x0 - 2 + cc;
        float v = 0.f;
        if (gy >= 0 && gy < Hh && gx >= 0 && gx < Ww)
            v = __ldg(&x[(size_t)(b * 3 + c) * HW + gy * Ww + gx]);
        sx[c][rr][cc] = v;
    }

    // ---- per-thread offset accumulators: 2 px x 18 channels ----
    float acc[18][2];
#pragma unroll
    for (int co = 0; co < 18; co++) {
        float bv = __ldg(&b2[co]);
        acc[co][0] = bv; acc[co][1] = bv;
    }

    const int r     = tid >> 5;        // 0..15 : tile row
    const int cbase = (tid & 31) * 2;  // 0..62 : tile col pair

    for (int ch0 = 0; ch0 < 64; ch0 += CHUNK) {
        __syncthreads();  // previous chunk's sy1/sw2/sw1t fully consumed

        // stage transposed conv2 weight chunk: [cl][tap][co]
        for (int i = tid; i < 18 * CHUNK * 9; i += NT) {
            int co = i / (CHUNK * 9);
            int rr = i % (CHUNK * 9);        // cl*9 + tap
            sw2[rr * WP + co] = __ldg(&w2[co * 576 + ch0 * 9 + rr]);
        }
        // stage transposed conv1 chunk weights: sw1t[tap] = {cl0,cl1,cl2,cl3}
        if (tid < 108) {
            int t  = tid >> 2;
            int cl = tid & 3;
            ((float*)sw1t)[t * 4 + cl] = sw1[(ch0 + cl) * 27 + t];
        }
        __syncthreads();

        // conv1 (+ReLU, image-masked): one task = 4 channels x 4 px.
        // 306 tasks over 512 threads -> single pass.
        for (int task = tid; task < Y1H * 17; task += NT) {
            int row = task / 17;
            int c0  = (task % 17) * 4;

            float a[4][4];
#pragma unroll
            for (int cl = 0; cl < 4; cl++) {
                float bv = sb1[ch0 + cl];
                a[cl][0] = bv; a[cl][1] = bv; a[cl][2] = bv; a[cl][3] = bv;
            }

#pragma unroll
            for (int c = 0; c < 3; c++) {
                float v[3][6];
#pragma unroll
                for (int dy = 0; dy < 3; dy++) {
                    float4 p4 = *(const float4*)&sx[c][row + dy][c0];
                    float2 p2 = *(const float2*)&sx[c][row + dy][c0 + 4];
                    v[dy][0] = p4.x; v[dy][1] = p4.y;
                    v[dy][2] = p4.z; v[dy][3] = p4.w;
                    v[dy][4] = p2.x; v[dy][5] = p2.y;
                }
#pragma unroll
                for (int t9 = 0; t9 < 9; t9++) {
                    const int dy = t9 / 3, dx = t9 % 3;
                    float4 w4 = sw1t[c * 9 + t9];
#pragma unroll
                    for (int j = 0; j < 4; j++) {
                        float vv = v[dy][dx + j];
                        a[0][j] = fmaf(vv, w4.x, a[0][j]);
                        a[1][j] = fmaf(vv, w4.y, a[1][j]);
                        a[2][j] = fmaf(vv, w4.z, a[2][j]);
                        a[3][j] = fmaf(vv, w4.w, a[3][j]);
                    }
                }
            }

            int gyy = y0 - 1 + row;
            bool okY = (gyy >= 0) && (gyy < Hh);
            bool okJ[4];
#pragma unroll
            for (int j = 0; j < 4; j++) {
                int col = c0 + j;
                int gx  = x0 - 1 + col;
                okJ[j] = okY && (col < Y1W) && (gx >= 0) && (gx < Ww);
            }
#pragma unroll
            for (int cl = 0; cl < 4; cl++) {
                float4 rv;
                rv.x = okJ[0] ? fmaxf(a[cl][0], 0.f) : 0.f;
                rv.y = okJ[1] ? fmaxf(a[cl][1], 0.f) : 0.f;
                rv.z = okJ[2] ? fmaxf(a[cl][2], 0.f) : 0.f;
                rv.w = okJ[3] ? fmaxf(a[cl][3], 0.f) : 0.f;
                *(float4*)&sy1[cl][row][c0] = rv;
            }
        }
        __syncthreads();

        // conv2 accumulate: 4 cin x 9 taps x 18 co x 2 px
#pragma unroll 1
        for (int cl = 0; cl < CHUNK; cl++) {
            float n[3][4];
#pragma unroll
            for (int r2 = 0; r2 < 3; r2++) {
                float2 pA = *(const float2*)&sy1[cl][r + r2][cbase];
                float2 pB = *(const float2*)&sy1[cl][r + r2][cbase + 2];
                n[r2][0] = pA.x; n[r2][1] = pA.y;
                n[r2][2] = pB.x; n[r2][3] = pB.y;
            }
#pragma unroll
            for (int t = 0; t < 9; t++) {
                const int ky = t / 3, kx = t % 3;
                const float* wp = &sw2[(cl * 9 + t) * WP];
                float w[18];
#pragma unroll
                for (int q = 0; q < 4; q++) {
                    float4 w4 = *(const float4*)(wp + 4 * q);
                    w[4*q] = w4.x; w[4*q+1] = w4.y; w[4*q+2] = w4.z; w[4*q+3] = w4.w;
                }
                float2 w2v = *(const float2*)(wp + 16);
                w[16] = w2v.x; w[17] = w2v.y;
                float nv0 = n[ky][kx + 0];
                float nv1 = n[ky][kx + 1];
#pragma unroll
                for (int co = 0; co < 18; co++) {
                    acc[co][0] = fmaf(nv0, w[co], acc[co][0]);
                    acc[co][1] = fmaf(nv1, w[co], acc[co][1]);
                }
            }
        }
    }

    // ---- deformable conv epilogue: offsets live in acc ----
    const int gy = y0 + r;
    const float* xb = x + (size_t)(b * 3) * HW;
    float o[3][2];
#pragma unroll
    for (int j = 0; j < 2; j++) {
        int gx = x0 + cbase + j;
        float a0 = sbd[0], a1 = sbd[1], a2 = sbd[2];
#pragma unroll
        for (int k = 0; k < 9; k++) {
            float dy = acc[2 * k][j];
            float dx = acc[2 * k + 1][j];
            float ys = (float)(gy + k / 3 - 1) + dy;
            float xs = (float)(gx + k % 3 - 1) + dx;
            float yf = floorf(ys), xf = floorf(xs);
            int iy0 = (int)yf, ix0 = (int)xf;
            float fy = ys - yf, fx = xs - xf;
            float s0 = 0.f, s1 = 0.f, s2 = 0.f;
#pragma unroll
            for (int cy = 0; cy < 2; cy++)
#pragma unroll
                for (int cx = 0; cx < 2; cx++) {
                    int iy = iy0 + cy, ix = ix0 + cx;
                    float wgt = (cy ? fy : 1.f - fy) * (cx ? fx : 1.f - fx);
                    bool ok = (iy >= 0) && (iy < Hh) && (ix >= 0) && (ix < Ww);
                    wgt = ok ? wgt : 0.f;
                    int idx = min(max(iy, 0), Hh - 1) * Ww + min(max(ix, 0), Ww - 1);
                    s0 = fmaf(wgt, __ldg(xb + idx), s0);
                    s1 = fmaf(wgt, __ldg(xb + HW + idx), s1);
                    s2 = fmaf(wgt, __ldg(xb + 2 * HW + idx), s2);
                }
            a0 = fmaf(s0, swd[ 0 + k], fmaf(s1, swd[ 9 + k], fmaf(s2, swd[18 + k], a0)));
            a1 = fmaf(s0, swd[27 + k], fmaf(s1, swd[36 + k], fmaf(s2, swd[45 + k], a1)));
            a2 = fmaf(s0, swd[54 + k], fmaf(s1, swd[63 + k], fmaf(s2, swd[72 + k], a2)));
        }
        o[0][j] = a0; o[1][j] = a1; o[2][j] = a2;
    }
#pragma unroll
    for (int c = 0; c < 3; c++) {
        float2 v;
        v.x = o[c][0]; v.y = o[c][1];
        *(float2*)&out[(size_t)(b * 3 + c) * HW + (size_t)gy * Ww + x0 + cbase] = v;
    }
}

extern "C" void kernel_launch(void* const* d_in, const int* in_sizes, int n_in,
                              void* d_out, int out_size)
{
    const float* x  = (const float*)d_in[0];
    const float* w1 = (const float*)d_in[1];
    const float* b1 = (const float*)d_in[2];
    const float* w2 = (const float*)d_in[3];
    const float* b2 = (const float*)d_in[4];
    const float* wd = (const float*)d_in[5];
    const float* bd = (const float*)d_in[6];
    float* out = (float*)d_out;

    dim3 grid(Ww / TW, Hh / TH, Bb);   // 8 x 32 x 8 = 2048 blocks
    fused_deform_kernel<<<grid, NT>>>(x, w1, b1, w2, b2, wd, bd, out);
}